// round 16
// baseline (speedup 1.0000x reference)
#include <cuda_runtime.h>
#include <cuda_fp16.h>
#include <math.h>
#include <stdint.h>

#define NTOK 2304
#define CIN  256
#define HID  512
#define QKV_M 1536

// Scratch (allocation-free rule: __device__ globals)
__device__ __half g_qkv[2u * 1536u * 2304u];  // qkv: [b][3*512][n]
__device__ __half g_att[2u * 512u * 2304u];   // attention out: [b][512][n]
__device__ float  g_inv[2048];                // inv L2 norms: [b][qk][512]
__device__ __half g_xh [2u * 256u * 2304u];   // x converted to fp16
__device__ __half g_wqh[1536u * 256u];        // w_qkv fp16
__device__ __half g_wph[256u * 512u];         // w_proj fp16
__device__ float  g_ssqp[2u * 1024u * 36u];   // per-(row, xblock, nwarp) ssq partials

// ---------------------------------------------------------------------------
// helpers
// ---------------------------------------------------------------------------
__device__ __forceinline__ uint32_t packh2(float a, float b) {
    __half2 h = __floats2half2_rn(a, b);
    return *reinterpret_cast<uint32_t*>(&h);
}

__device__ __forceinline__ void mmah(float* c, const uint32_t* a,
                                     uint32_t b0, uint32_t b1) {
    asm volatile(
        "mma.sync.aligned.m16n8k16.row.col.f32.f16.f16.f32 "
        "{%0,%1,%2,%3}, {%4,%5,%6,%7}, {%8,%9}, {%0,%1,%2,%3};\n"
        : "+f"(c[0]), "+f"(c[1]), "+f"(c[2]), "+f"(c[3])
        : "r"(a[0]), "r"(a[1]), "r"(a[2]), "r"(a[3]), "r"(b0), "r"(b1));
}

__device__ __forceinline__ void ldmx2t(uint32_t& r0, uint32_t& r1, const __half* p) {
    uint32_t addr = (uint32_t)__cvta_generic_to_shared(p);
    asm volatile("ldmatrix.sync.aligned.m8n8.x2.trans.shared.b16 {%0,%1}, [%2];"
                 : "=r"(r0), "=r"(r1) : "r"(addr));
}

__device__ __forceinline__ void ldmx4t(uint32_t& r0, uint32_t& r1,
                                       uint32_t& r2, uint32_t& r3, const __half* p) {
    uint32_t addr = (uint32_t)__cvta_generic_to_shared(p);
    asm volatile("ldmatrix.sync.aligned.m8n8.x4.trans.shared.b16 {%0,%1,%2,%3}, [%4];"
                 : "=r"(r0), "=r"(r1), "=r"(r2), "=r"(r3) : "r"(addr));
}

__device__ __forceinline__ void ldmx4(uint32_t* r, const __half* p) {
    uint32_t addr = (uint32_t)__cvta_generic_to_shared(p);
    asm volatile("ldmatrix.sync.aligned.m8n8.x4.shared.b16 {%0,%1,%2,%3}, [%4];"
                 : "=r"(r[0]), "=r"(r[1]), "=r"(r[2]), "=r"(r[3]) : "r"(addr));
}

__device__ __forceinline__ void cpasync16(const __half* smem_dst, const __half* gsrc) {
    uint32_t s = (uint32_t)__cvta_generic_to_shared(smem_dst);
    asm volatile("cp.async.ca.shared.global [%0], [%1], 16;\n" :: "r"(s), "l"(gsrc));
}
__device__ __forceinline__ void cpcommit() {
    asm volatile("cp.async.commit_group;\n");
}

// ---------------------------------------------------------------------------
// One-shot fp32 -> fp16 conversion of x, w_qkv, w_proj.
// ---------------------------------------------------------------------------
#define CVT_N1 (2u * 256u * 2304u)
#define CVT_N2 (1536u * 256u)
#define CVT_N3 (256u * 512u)

__global__ __launch_bounds__(256) void cvt3(
    const float* __restrict__ x, const float* __restrict__ wq,
    const float* __restrict__ wp)
{
    const unsigned idx = (blockIdx.x * 256u + threadIdx.x) * 8u;
    const float* src;
    __half* dst;
    if (idx < CVT_N1)              { src = x  + idx;                 dst = g_xh  + idx; }
    else if (idx < CVT_N1 + CVT_N2){ src = wq + (idx - CVT_N1);      dst = g_wqh + (idx - CVT_N1); }
    else                           { src = wp + (idx - CVT_N1 - CVT_N2); dst = g_wph + (idx - CVT_N1 - CVT_N2); }
    float4 a = *(const float4*)src;
    float4 b = *(const float4*)(src + 4);
    uint4 o;
    o.x = packh2(a.x, a.y); o.y = packh2(a.z, a.w);
    o.z = packh2(b.x, b.y); o.w = packh2(b.z, b.w);
    *(uint4*)dst = o;
}

// ---------------------------------------------------------------------------
// all-fp16 tensor-core GEMM with 3-stage cp.async pipeline.
// C = A(MxK)*B(KxN) (+bias); A,B fp16 row-major; C fp32 or fp16 (TC).
// SSQ: emit deterministic per-(row, xblock, nwarp) sum-of-squares partials
// for batch-rows < 1024 (the q/k rows) into ssqp[(bz*1024+row)*36 + slot].
// ---------------------------------------------------------------------------
template<int BM, int BN, int WMN, int WNN, typename TC, bool SSQ>
__global__ __launch_bounds__(WMN * WNN * 32) void h16gemm(
    const __half* __restrict__ A, const __half* __restrict__ Bg,
    TC* __restrict__ Cg, const float* __restrict__ bias,
    float* __restrict__ ssqp,
    int M, int N, int K, long long strideB, long long strideC)
{
    constexpr int THREADS = WMN * WNN * 32;
    constexpr int BK  = 32;
    constexpr int AST = BK + 8;      // 40 halves = 80B rows (16B-multiple)
    constexpr int BST = BN + 8;
    constexpr int WM = BM / WMN;
    constexpr int WN = BN / WNN;
    constexpr int MT = WM / 16;
    constexpr int NT = WN / 8;
    constexpr int A_CH = BM * 4 / THREADS;          // 16B chunks per thread
    constexpr int B_CH = (BK * BN / 8) / THREADS;
    constexpr bool CH = (sizeof(TC) == 2);

    __shared__ __half As[3][BM * AST];
    __shared__ __half Bs[3][BK * BST];

    const __half* B = Bg + (long long)blockIdx.z * strideB;
    TC*           C = Cg + (long long)blockIdx.z * strideC;

    const int m0 = blockIdx.y * BM;
    const int n0 = blockIdx.x * BN;
    const int tid  = threadIdx.x;
    const int w    = tid >> 5;
    const int lane = tid & 31;
    const int g    = lane >> 2;
    const int tg   = lane & 3;
    const int wm   = (w % WMN) * WM;
    const int wn   = (w / WMN) * WN;

    float acc[MT][NT][4];
#pragma unroll
    for (int mt = 0; mt < MT; mt++)
#pragma unroll
        for (int nt = 0; nt < NT; nt++)
#pragma unroll
            for (int j = 0; j < 4; j++) acc[mt][nt][j] = 0.0f;

    int arow[A_CH], acol[A_CH], brow[B_CH], bcol[B_CH];
#pragma unroll
    for (int i = 0; i < A_CH; i++) {
        int idx = i * THREADS + tid;
        arow[i] = idx >> 2; acol[i] = (idx & 3) * 8;
    }
#pragma unroll
    for (int i = 0; i < B_CH; i++) {
        int idx = i * THREADS + tid;
        brow[i] = idx / (BN / 8); bcol[i] = (idx % (BN / 8)) * 8;
    }

    auto issue_tile = [&](int st, int k0) {
#pragma unroll
        for (int i = 0; i < A_CH; i++)
            cpasync16(&As[st][arow[i] * AST + acol[i]],
                      A + (long long)(m0 + arow[i]) * K + k0 + acol[i]);
#pragma unroll
        for (int i = 0; i < B_CH; i++)
            cpasync16(&Bs[st][brow[i] * BST + bcol[i]],
                      B + (long long)(k0 + brow[i]) * N + n0 + bcol[i]);
        cpcommit();
    };

    const int nk = K / BK;
    issue_tile(0, 0);
    if (nk > 1) issue_tile(1, BK);

    for (int t = 0; t < nk; t++) {
        if (t + 1 < nk)
            asm volatile("cp.async.wait_group 1;\n");
        else
            asm volatile("cp.async.wait_group 0;\n");
        __syncthreads();
        if (t + 2 < nk) issue_tile((t + 2) % 3, (t + 2) * BK);

        const int cur = t % 3;
#pragma unroll
        for (int ks = 0; ks < BK; ks += 16) {
            uint32_t af[MT][4];
#pragma unroll
            for (int mt = 0; mt < MT; mt++) {
                const int r = wm + mt * 16 + g;
                af[mt][0] = *(const uint32_t*)&As[cur][r * AST + ks + 2 * tg];
                af[mt][1] = *(const uint32_t*)&As[cur][(r + 8) * AST + ks + 2 * tg];
                af[mt][2] = *(const uint32_t*)&As[cur][r * AST + ks + 2 * tg + 8];
                af[mt][3] = *(const uint32_t*)&As[cur][(r + 8) * AST + ks + 2 * tg + 8];
            }
#pragma unroll
            for (int nt = 0; nt < NT; nt++) {
                uint32_t b0, b1;
                ldmx2t(b0, b1, &Bs[cur][(ks + (lane & 15)) * BST + wn + nt * 8]);
#pragma unroll
                for (int mt = 0; mt < MT; mt++)
                    mmah(acc[mt][nt], af[mt], b0, b1);
            }
        }
    }

    // Epilogue
#pragma unroll
    for (int mt = 0; mt < MT; mt++) {
        const int r0 = m0 + wm + mt * 16 + g;
        const float bs0 = bias ? bias[r0]     : 0.0f;
        const float bs1 = bias ? bias[r0 + 8] : 0.0f;
#pragma unroll
        for (int nt = 0; nt < NT; nt++) {
            const int cidx = n0 + wn + nt * 8 + 2 * tg;
            if constexpr (CH) {
                *(__half2*)(C + (long long)r0 * N + cidx) =
                    __floats2half2_rn(acc[mt][nt][0] + bs0, acc[mt][nt][1] + bs0);
                *(__half2*)(C + (long long)(r0 + 8) * N + cidx) =
                    __floats2half2_rn(acc[mt][nt][2] + bs1, acc[mt][nt][3] + bs1);
            } else {
                *(float2*)(C + (long long)r0 * N + cidx) =
                    make_float2(acc[mt][nt][0] + bs0, acc[mt][nt][1] + bs0);
                *(float2*)(C + (long long)(r0 + 8) * N + cidx) =
                    make_float2(acc[mt][nt][2] + bs1, acc[mt][nt][3] + bs1);
            }
        }
    }

    // Fused sum-of-squares partials for L2 norms (q/k rows only).
    if constexpr (SSQ) {
        if (m0 < 1024) {
            const int slot = blockIdx.x * 2 + (w / WMN);
#pragma unroll
            for (int mt = 0; mt < MT; mt++) {
                float slo = 0.0f, shi = 0.0f;
#pragma unroll
                for (int nt = 0; nt < NT; nt++) {
                    slo += acc[mt][nt][0] * acc[mt][nt][0]
                         + acc[mt][nt][1] * acc[mt][nt][1];
                    shi += acc[mt][nt][2] * acc[mt][nt][2]
                         + acc[mt][nt][3] * acc[mt][nt][3];
                }
                slo += __shfl_xor_sync(0xffffffffu, slo, 1);
                slo += __shfl_xor_sync(0xffffffffu, slo, 2);
                shi += __shfl_xor_sync(0xffffffffu, shi, 1);
                shi += __shfl_xor_sync(0xffffffffu, shi, 2);
                if (tg == 0) {
                    const int r = m0 + wm + mt * 16 + g;
                    ssqp[((long long)blockIdx.z * 1024 + r) * 36 + slot]     = slo;
                    ssqp[((long long)blockIdx.z * 1024 + r + 8) * 36 + slot] = shi;
                }
            }
        }
    }
}

// ---------------------------------------------------------------------------
// Finalize inverse L2 norms: inv[i] = 1/max(sqrt(sum of 36 partials), 1e-12).
// ---------------------------------------------------------------------------
__global__ __launch_bounds__(256) void fin_inv(const float* __restrict__ ssqp,
                                               float* __restrict__ inv)
{
    const int i = blockIdx.x * 256 + threadIdx.x;   // 0..2047
    const float* p = ssqp + (long long)i * 36;
    float s = 0.0f;
#pragma unroll
    for (int j = 0; j < 36; j++) s += p[j];
    inv[i] = 1.0f / fmaxf(sqrtf(s), 1e-12f);
}

// ---------------------------------------------------------------------------
// fp16 flash attention (unchanged winner from R15): unshifted exp2 softmax,
// 4 warps x 32 n-rows, 128 threads, 64 kv-tile, 3-stage cp.async pipeline.
// ---------------------------------------------------------------------------
#define SKT 72
#define NST 3

__global__ __launch_bounds__(128, 2) void flash_attn_h(
    const __half* __restrict__ qkv, const float* __restrict__ inv,
    __half* __restrict__ outp)
{
    __shared__ __half sK[NST][64 * SKT];
    __shared__ __half sV[NST][64 * SKT];

    const int b  = blockIdx.y >> 3;
    const int h  = blockIdx.y & 7;
    const int n0 = blockIdx.x * 128;

    const __half* Q  = qkv + ((long long)(b * 3 * HID + h * 64)) * NTOK;
    const __half* Kp = Q + (long long)HID * NTOK;
    const __half* Vp = Q + 2LL * HID * NTOK;
    const float* invQ = inv + b * 1024 + h * 64;
    const float* invK = invQ + 512;

    const int tid  = threadIdx.x;
    const int w    = tid >> 5;        // 0..3, owns n rows [w*32, w*32+32)
    const int lane = tid & 31;
    const int g    = lane >> 2;
    const int tg   = lane & 3;

    const float LG2E = 1.4426950408889634f;

    // ldmatrix.x4 lane-address components.
    const int l_row = (lane & 7) + ((lane >> 3) & 1) * 8;
    const int l_col8 = (lane >> 4) * 8;

    // cp.async tile loader: 4 chunks of 16B per thread per array (128 thr).
    int dd[4], mm[4];
#pragma unroll
    for (int p = 0; p < 4; p++) {
        const int idx = (p * 128 + tid) * 8;
        dd[p] = idx >> 6; mm[p] = idx & 63;
    }
    auto issue_tile = [&](int st, int mbase) {
#pragma unroll
        for (int p = 0; p < 4; p++)
            cpasync16(&sK[st][dd[p] * SKT + mm[p]],
                      Kp + (long long)dd[p] * NTOK + mbase + mm[p]);
#pragma unroll
        for (int p = 0; p < 4; p++)
            cpasync16(&sV[st][dd[p] * SKT + mm[p]],
                      Vp + (long long)dd[p] * NTOK + mbase + mm[p]);
        cpcommit();
    };

    // Q^T A-fragments for 32 rows (2 groups of 16), scaled by invQ*invK*lg2e.
    uint32_t qa[2][4][4];
    {
#pragma unroll
        for (int u = 0; u < 2; u++) {
            const int nA = n0 + w * 32 + u * 16 + g;
#pragma unroll
            for (int kk = 0; kk < 4; kk++) {
                const int ddq = kk * 16 + 2 * tg;
                const float s0 = invQ[ddq]     * invK[ddq]     * LG2E;
                const float s1 = invQ[ddq + 1] * invK[ddq + 1] * LG2E;
                const float s8 = invQ[ddq + 8] * invK[ddq + 8] * LG2E;
                const float s9 = invQ[ddq + 9] * invK[ddq + 9] * LG2E;
                qa[u][kk][0] = packh2(__half2float(Q[(long long)ddq * NTOK + nA]) * s0,
                                      __half2float(Q[(long long)(ddq + 1) * NTOK + nA]) * s1);
                qa[u][kk][1] = packh2(__half2float(Q[(long long)ddq * NTOK + nA + 8]) * s0,
                                      __half2float(Q[(long long)(ddq + 1) * NTOK + nA + 8]) * s1);
                qa[u][kk][2] = packh2(__half2float(Q[(long long)(ddq + 8) * NTOK + nA]) * s8,
                                      __half2float(Q[(long long)(ddq + 9) * NTOK + nA]) * s9);
                qa[u][kk][3] = packh2(__half2float(Q[(long long)(ddq + 8) * NTOK + nA + 8]) * s8,
                                      __half2float(Q[(long long)(ddq + 9) * NTOK + nA + 8]) * s9);
            }
        }
    }

    // O^T accumulators: all 64 d (4 m-tiles) x warp's 32 n (4 n-groups of 8).
    float oc[4][4][4];
#pragma unroll
    for (int mt = 0; mt < 4; mt++)
#pragma unroll
        for (int nt = 0; nt < 4; nt++)
#pragma unroll
            for (int j = 0; j < 4; j++) oc[mt][nt][j] = 0.0f;

    float rsum[4] = {0.0f, 0.0f, 0.0f, 0.0f};   // lane-partial row sums

    const int src_lo = 8 * tg;       // lane holding row 2tg of an 8-group
    const int src_hi = 8 * tg + 4;   // lane holding row 2tg+1

    // Prologue: stage tiles 0 and 1.
    issue_tile(0, 0);
    issue_tile(1, 64);

    const int NKV = NTOK / 64;       // 36
    int cur = 0;
    for (int t = 0; t < NKV; t++) {
        if (t + 1 < NKV)
            asm volatile("cp.async.wait_group 1;\n");
        else
            asm volatile("cp.async.wait_group 0;\n");
        __syncthreads();
        if (t + 2 < NKV) issue_tile((t + 2) % NST, (t + 2) * 64);

        const __half* cK = sK[cur];
        const __half* cV = sV[cur];

        // ---- Phase A: S = Q^T K (32 n-rows x 64 m per warp) ----
        float sc[2][8][4];
#pragma unroll
        for (int u = 0; u < 2; u++)
#pragma unroll
            for (int tt = 0; tt < 8; tt++)
#pragma unroll
                for (int j = 0; j < 4; j++) sc[u][tt][j] = 0.0f;

#pragma unroll
        for (int kk = 0; kk < 4; kk++) {
            const __half* krow = &cK[(kk * 16 + l_row) * SKT + l_col8];
#pragma unroll
            for (int tt = 0; tt < 8; tt += 2) {
                uint32_t b0, b1, b2, b3;
                ldmx4t(b0, b1, b2, b3, krow + tt * 8);   // K frags, tiles tt/tt+1
                mmah(sc[0][tt],     qa[0][kk], b0, b1);
                mmah(sc[0][tt + 1], qa[0][kk], b2, b3);
                mmah(sc[1][tt],     qa[1][kk], b0, b1);
                mmah(sc[1][tt + 1], qa[1][kk], b2, b3);
            }
        }

        // ---- Unshifted softmax numerators: P = exp2(sc) ----
        uint32_t ph[8][4];            // [m-tile][n-group u*2+r]
#pragma unroll
        for (int u = 0; u < 2; u++)
#pragma unroll
        for (int r = 0; r < 2; r++) {
            const int q4 = u * 2 + r;
            float ps = 0.0f;
#pragma unroll
            for (int tt = 0; tt < 8; tt++) {
                float e0 = exp2f(sc[u][tt][2 * r]);
                float e1 = exp2f(sc[u][tt][2 * r + 1]);
                ps += e0 + e1;
                ph[tt][q4] = packh2(e0, e1);
            }
            rsum[q4] += ps;           // lane-partial; reduced in epilogue
        }

        // ---- Phase B: O^T += V * P^T (each V fragment feeds 4 mma) ----
#pragma unroll
        for (int kk = 0; kk < 4; kk++) {
#pragma unroll
            for (int mt = 0; mt < 4; mt++) {
                uint32_t a[4];
                ldmx4(a, &cV[(mt * 16 + l_row) * SKT + kk * 16 + l_col8]);
#pragma unroll
                for (int nt = 0; nt < 4; nt++)
                    mmah(oc[mt][nt], a, ph[2 * kk][nt], ph[2 * kk + 1][nt]);
            }
        }

        cur = (cur + 1) % NST;
    }

    // ---- Epilogue: reduce rsum across the 4-lane groups, then normalize ----
    float iv[4][2];
#pragma unroll
    for (int nt = 0; nt < 4; nt++) {
        rsum[nt] += __shfl_xor_sync(0xffffffffu, rsum[nt], 1);
        rsum[nt] += __shfl_xor_sync(0xffffffffu, rsum[nt], 2);
        iv[nt][0] = 1.0f / __shfl_sync(0xffffffffu, rsum[nt], src_lo);
        iv[nt][1] = 1.0f / __shfl_sync(0xffffffffu, rsum[nt], src_hi);
    }

    __half* Op = outp + ((long long)(b * HID + h * 64)) * NTOK + n0 + w * 32;
#pragma unroll
    for (int mt = 0; mt < 4; mt++) {
#pragma unroll
        for (int nt = 0; nt < 4; nt++) {
            const int ncol = nt * 8 + 2 * tg;
            __half* p0 = Op + (long long)(mt * 16 + g) * NTOK + ncol;
            *(__half2*)p0 = __floats2half2_rn(oc[mt][nt][0] * iv[nt][0],
                                              oc[mt][nt][1] * iv[nt][1]);
            __half* p1 = Op + (long long)(mt * 16 + g + 8) * NTOK + ncol;
            *(__half2*)p1 = __floats2half2_rn(oc[mt][nt][2] * iv[nt][0],
                                              oc[mt][nt][3] * iv[nt][1]);
        }
    }
}

// ---------------------------------------------------------------------------
extern "C" void kernel_launch(void* const* d_in, const int* in_sizes, int n_in,
                              void* d_out, int out_size)
{
    const float* x      = (const float*)d_in[0];   // (2, 256, 48, 48)
    const float* w_qkv  = (const float*)d_in[1];   // (1536, 256)
    const float* w_proj = (const float*)d_in[2];   // (256, 512)
    const float* b_proj = (const float*)d_in[3];   // (256,)
    float* y = (float*)d_out;                      // (2, 256, 48, 48)

    __half *qkv_ptr = nullptr, *att_ptr = nullptr, *xh = nullptr,
           *wqh = nullptr, *wph = nullptr;
    float  *inv_ptr = nullptr, *ssq_ptr = nullptr;
    cudaGetSymbolAddress((void**)&qkv_ptr, g_qkv);
    cudaGetSymbolAddress((void**)&att_ptr, g_att);
    cudaGetSymbolAddress((void**)&inv_ptr, g_inv);
    cudaGetSymbolAddress((void**)&xh,  g_xh);
    cudaGetSymbolAddress((void**)&wqh, g_wqh);
    cudaGetSymbolAddress((void**)&wph, g_wph);
    cudaGetSymbolAddress((void**)&ssq_ptr, g_ssqp);

    // 0) convert inputs to fp16
    cvt3<<<(CVT_N1 + CVT_N2 + CVT_N3) / (256 * 8), 256>>>(x, w_qkv, w_proj);

    // 1) qkv = w_qkv @ x : [1536,256] x [256,2304] per batch, fp16 out.
    //    64x128 tiles -> 864 CTAs (balanced waves) + fused ssq partials.
    h16gemm<64, 128, 2, 2, __half, true>
        <<<dim3(NTOK / 128, QKV_M / 64, 2), 128>>>(
        wqh, xh, qkv_ptr, nullptr, ssq_ptr,
        QKV_M, NTOK, CIN,
        (long long)CIN * NTOK, (long long)QKV_M * NTOK);

    // 2) finalize inverse L2 norms from the 36 partials per row
    fin_inv<<<8, 256>>>(ssq_ptr, inv_ptr);

    // 3) flash attention: 18 q-tiles x 16 (b,h) heads, 128 threads
    flash_attn_h<<<dim3(NTOK / 128, 16), 128>>>(qkv_ptr, inv_ptr, att_ptr);

    // 4) y = w_proj @ att + bias : [256,512] x [512,2304] per batch, fp32 out
    h16gemm<64, 32, 2, 2, float, false>
        <<<dim3(NTOK / 32, CIN / 64, 2), 128>>>(
        wph, att_ptr, y, b_proj, nullptr,
        CIN, NTOK, HID,
        (long long)HID * NTOK, (long long)CIN * NTOK);
}

// round 17
// speedup vs baseline: 1.0735x; 1.0735x over previous
#include <cuda_runtime.h>
#include <cuda_fp16.h>
#include <math.h>
#include <stdint.h>

#define NTOK 2304
#define CIN  256
#define HID  512
#define QKV_M 1536

// Scratch (allocation-free rule: __device__ globals)
__device__ __half g_qkv[2u * 1536u * 2304u];  // qkv: [b][3*512][n]
__device__ __half g_att[2u * 512u * 2304u];   // attention out: [b][512][n]
__device__ __half g_xh [2u * 256u * 2304u];   // x converted to fp16
__device__ __half g_wqh[1536u * 256u];        // w_qkv fp16
__device__ __half g_wph[256u * 512u];         // w_proj fp16
__device__ float  g_ssqp[2u * 1024u * 36u];   // per-(row, xblock, nwarp) ssq partials

// ---------------------------------------------------------------------------
// helpers
// ---------------------------------------------------------------------------
__device__ __forceinline__ uint32_t packh2(float a, float b) {
    __half2 h = __floats2half2_rn(a, b);
    return *reinterpret_cast<uint32_t*>(&h);
}

__device__ __forceinline__ void mmah(float* c, const uint32_t* a,
                                     uint32_t b0, uint32_t b1) {
    asm volatile(
        "mma.sync.aligned.m16n8k16.row.col.f32.f16.f16.f32 "
        "{%0,%1,%2,%3}, {%4,%5,%6,%7}, {%8,%9}, {%0,%1,%2,%3};\n"
        : "+f"(c[0]), "+f"(c[1]), "+f"(c[2]), "+f"(c[3])
        : "r"(a[0]), "r"(a[1]), "r"(a[2]), "r"(a[3]), "r"(b0), "r"(b1));
}

__device__ __forceinline__ void ldmx2t(uint32_t& r0, uint32_t& r1, const __half* p) {
    uint32_t addr = (uint32_t)__cvta_generic_to_shared(p);
    asm volatile("ldmatrix.sync.aligned.m8n8.x2.trans.shared.b16 {%0,%1}, [%2];"
                 : "=r"(r0), "=r"(r1) : "r"(addr));
}

__device__ __forceinline__ void ldmx4t(uint32_t& r0, uint32_t& r1,
                                       uint32_t& r2, uint32_t& r3, const __half* p) {
    uint32_t addr = (uint32_t)__cvta_generic_to_shared(p);
    asm volatile("ldmatrix.sync.aligned.m8n8.x4.trans.shared.b16 {%0,%1,%2,%3}, [%4];"
                 : "=r"(r0), "=r"(r1), "=r"(r2), "=r"(r3) : "r"(addr));
}

__device__ __forceinline__ void ldmx4(uint32_t* r, const __half* p) {
    uint32_t addr = (uint32_t)__cvta_generic_to_shared(p);
    asm volatile("ldmatrix.sync.aligned.m8n8.x4.shared.b16 {%0,%1,%2,%3}, [%4];"
                 : "=r"(r[0]), "=r"(r[1]), "=r"(r[2]), "=r"(r[3]) : "r"(addr));
}

__device__ __forceinline__ void cpasync16(const __half* smem_dst, const __half* gsrc) {
    uint32_t s = (uint32_t)__cvta_generic_to_shared(smem_dst);
    asm volatile("cp.async.ca.shared.global [%0], [%1], 16;\n" :: "r"(s), "l"(gsrc));
}
__device__ __forceinline__ void cpcommit() {
    asm volatile("cp.async.commit_group;\n");
}

// ---------------------------------------------------------------------------
// One-shot fp32 -> fp16 conversion of x, w_qkv, w_proj.
// ---------------------------------------------------------------------------
#define CVT_N1 (2u * 256u * 2304u)
#define CVT_N2 (1536u * 256u)
#define CVT_N3 (256u * 512u)

__global__ __launch_bounds__(256) void cvt3(
    const float* __restrict__ x, const float* __restrict__ wq,
    const float* __restrict__ wp)
{
    const unsigned idx = (blockIdx.x * 256u + threadIdx.x) * 8u;
    const float* src;
    __half* dst;
    if (idx < CVT_N1)              { src = x  + idx;                 dst = g_xh  + idx; }
    else if (idx < CVT_N1 + CVT_N2){ src = wq + (idx - CVT_N1);      dst = g_wqh + (idx - CVT_N1); }
    else                           { src = wp + (idx - CVT_N1 - CVT_N2); dst = g_wph + (idx - CVT_N1 - CVT_N2); }
    float4 a = *(const float4*)src;
    float4 b = *(const float4*)(src + 4);
    uint4 o;
    o.x = packh2(a.x, a.y); o.y = packh2(a.z, a.w);
    o.z = packh2(b.x, b.y); o.w = packh2(b.z, b.w);
    *(uint4*)dst = o;
}

// ---------------------------------------------------------------------------
// all-fp16 tensor-core GEMM with 3-stage cp.async pipeline.
// C = A(MxK)*B(KxN) (+bias); A,B fp16 row-major; C fp32 or fp16 (TC).
// SSQ: emit deterministic per-(row, xblock, nwarpcol) sum-of-squares partials
// for batch-rows < 1024 (the q/k rows) into ssqp[(bz*1024+row)*36 + slot].
// ---------------------------------------------------------------------------
template<int BM, int BN, int WMN, int WNN, typename TC, bool SSQ>
__global__ __launch_bounds__(WMN * WNN * 32) void h16gemm(
    const __half* __restrict__ A, const __half* __restrict__ Bg,
    TC* __restrict__ Cg, const float* __restrict__ bias,
    float* __restrict__ ssqp,
    int M, int N, int K, long long strideB, long long strideC)
{
    constexpr int THREADS = WMN * WNN * 32;
    constexpr int BK  = 32;
    constexpr int AST = BK + 8;      // 40 halves = 80B rows (16B-multiple)
    constexpr int BST = BN + 8;
    constexpr int WM = BM / WMN;
    constexpr int WN = BN / WNN;
    constexpr int MT = WM / 16;
    constexpr int NT = WN / 8;
    constexpr int A_CH = BM * 4 / THREADS;          // 16B chunks per thread
    constexpr int B_CH = (BK * BN / 8) / THREADS;
    constexpr bool CH = (sizeof(TC) == 2);

    __shared__ __half As[3][BM * AST];
    __shared__ __half Bs[3][BK * BST];

    const __half* B = Bg + (long long)blockIdx.z * strideB;
    TC*           C = Cg + (long long)blockIdx.z * strideC;

    const int m0 = blockIdx.y * BM;
    const int n0 = blockIdx.x * BN;
    const int tid  = threadIdx.x;
    const int w    = tid >> 5;
    const int lane = tid & 31;
    const int g    = lane >> 2;
    const int tg   = lane & 3;
    const int wm   = (w % WMN) * WM;
    const int wn   = (w / WMN) * WN;

    float acc[MT][NT][4];
#pragma unroll
    for (int mt = 0; mt < MT; mt++)
#pragma unroll
        for (int nt = 0; nt < NT; nt++)
#pragma unroll
            for (int j = 0; j < 4; j++) acc[mt][nt][j] = 0.0f;

    int arow[A_CH], acol[A_CH], brow[B_CH], bcol[B_CH];
#pragma unroll
    for (int i = 0; i < A_CH; i++) {
        int idx = i * THREADS + tid;
        arow[i] = idx >> 2; acol[i] = (idx & 3) * 8;
    }
#pragma unroll
    for (int i = 0; i < B_CH; i++) {
        int idx = i * THREADS + tid;
        brow[i] = idx / (BN / 8); bcol[i] = (idx % (BN / 8)) * 8;
    }

    auto issue_tile = [&](int st, int k0) {
#pragma unroll
        for (int i = 0; i < A_CH; i++)
            cpasync16(&As[st][arow[i] * AST + acol[i]],
                      A + (long long)(m0 + arow[i]) * K + k0 + acol[i]);
#pragma unroll
        for (int i = 0; i < B_CH; i++)
            cpasync16(&Bs[st][brow[i] * BST + bcol[i]],
                      B + (long long)(k0 + brow[i]) * N + n0 + bcol[i]);
        cpcommit();
    };

    const int nk = K / BK;
    issue_tile(0, 0);
    if (nk > 1) issue_tile(1, BK);

    for (int t = 0; t < nk; t++) {
        if (t + 1 < nk)
            asm volatile("cp.async.wait_group 1;\n");
        else
            asm volatile("cp.async.wait_group 0;\n");
        __syncthreads();
        if (t + 2 < nk) issue_tile((t + 2) % 3, (t + 2) * BK);

        const int cur = t % 3;
#pragma unroll
        for (int ks = 0; ks < BK; ks += 16) {
            uint32_t af[MT][4];
#pragma unroll
            for (int mt = 0; mt < MT; mt++) {
                const int r = wm + mt * 16 + g;
                af[mt][0] = *(const uint32_t*)&As[cur][r * AST + ks + 2 * tg];
                af[mt][1] = *(const uint32_t*)&As[cur][(r + 8) * AST + ks + 2 * tg];
                af[mt][2] = *(const uint32_t*)&As[cur][r * AST + ks + 2 * tg + 8];
                af[mt][3] = *(const uint32_t*)&As[cur][(r + 8) * AST + ks + 2 * tg + 8];
            }
#pragma unroll
            for (int nt = 0; nt < NT; nt++) {
                uint32_t b0, b1;
                ldmx2t(b0, b1, &Bs[cur][(ks + (lane & 15)) * BST + wn + nt * 8]);
#pragma unroll
                for (int mt = 0; mt < MT; mt++)
                    mmah(acc[mt][nt], af[mt], b0, b1);
            }
        }
    }

    // Epilogue
#pragma unroll
    for (int mt = 0; mt < MT; mt++) {
        const int r0 = m0 + wm + mt * 16 + g;
        const float bs0 = bias ? bias[r0]     : 0.0f;
        const float bs1 = bias ? bias[r0 + 8] : 0.0f;
#pragma unroll
        for (int nt = 0; nt < NT; nt++) {
            const int cidx = n0 + wn + nt * 8 + 2 * tg;
            if constexpr (CH) {
                *(__half2*)(C + (long long)r0 * N + cidx) =
                    __floats2half2_rn(acc[mt][nt][0] + bs0, acc[mt][nt][1] + bs0);
                *(__half2*)(C + (long long)(r0 + 8) * N + cidx) =
                    __floats2half2_rn(acc[mt][nt][2] + bs1, acc[mt][nt][3] + bs1);
            } else {
                *(float2*)(C + (long long)r0 * N + cidx) =
                    make_float2(acc[mt][nt][0] + bs0, acc[mt][nt][1] + bs0);
                *(float2*)(C + (long long)(r0 + 8) * N + cidx) =
                    make_float2(acc[mt][nt][2] + bs1, acc[mt][nt][3] + bs1);
            }
        }
    }

    // Fused sum-of-squares partials for L2 norms (q/k rows only).
    // slot = xblock * WNN + warp n-column  (NTOK/BN * WNN = 36 slots for qkv).
    if constexpr (SSQ) {
        if (m0 < 1024) {
            const int slot = blockIdx.x * WNN + (w / WMN);
#pragma unroll
            for (int mt = 0; mt < MT; mt++) {
                float slo = 0.0f, shi = 0.0f;
#pragma unroll
                for (int nt = 0; nt < NT; nt++) {
                    slo += acc[mt][nt][0] * acc[mt][nt][0]
                         + acc[mt][nt][1] * acc[mt][nt][1];
                    shi += acc[mt][nt][2] * acc[mt][nt][2]
                         + acc[mt][nt][3] * acc[mt][nt][3];
                }
                slo += __shfl_xor_sync(0xffffffffu, slo, 1);
                slo += __shfl_xor_sync(0xffffffffu, slo, 2);
                shi += __shfl_xor_sync(0xffffffffu, shi, 1);
                shi += __shfl_xor_sync(0xffffffffu, shi, 2);
                if (tg == 0) {
                    const int r = m0 + wm + mt * 16 + g;
                    ssqp[((long long)blockIdx.z * 1024 + r) * 36 + slot]     = slo;
                    ssqp[((long long)blockIdx.z * 1024 + r + 8) * 36 + slot] = shi;
                }
            }
        }
    }
}

// ---------------------------------------------------------------------------
// fp16 flash attention: unshifted exp2 softmax, 4 warps x 32 n-rows,
// 128 threads, 64 kv-tile, 3-stage cp.async pipeline. Inverse L2 norms are
// computed inline from the qkv-fused ssq partials (128 rows x 36 partials
// per CTA, overlapped with the prologue cp.async) -- no separate kernel.
// ---------------------------------------------------------------------------
#define SKT 72
#define NST 3

__global__ __launch_bounds__(128, 2) void flash_attn_h(
    const __half* __restrict__ qkv, const float* __restrict__ ssqp,
    __half* __restrict__ outp)
{
    __shared__ __half sK[NST][64 * SKT];
    __shared__ __half sV[NST][64 * SKT];
    __shared__ float  sInv[128];     // [0:64) q-row invs, [64:128) k-row invs

    const int b  = blockIdx.y >> 3;
    const int h  = blockIdx.y & 7;
    const int n0 = blockIdx.x * 128;

    const __half* Q  = qkv + ((long long)(b * 3 * HID + h * 64)) * NTOK;
    const __half* Kp = Q + (long long)HID * NTOK;
    const __half* Vp = Q + 2LL * HID * NTOK;

    const int tid  = threadIdx.x;
    const int w    = tid >> 5;        // 0..3, owns n rows [w*32, w*32+32)
    const int lane = tid & 31;
    const int g    = lane >> 2;
    const int tg   = lane & 3;

    const float LG2E = 1.4426950408889634f;

    // ldmatrix.x4 lane-address components.
    const int l_row = (lane & 7) + ((lane >> 3) & 1) * 8;
    const int l_col8 = (lane >> 4) * 8;

    // cp.async tile loader: 4 chunks of 16B per thread per array (128 thr).
    int dd[4], mm[4];
#pragma unroll
    for (int p = 0; p < 4; p++) {
        const int idx = (p * 128 + tid) * 8;
        dd[p] = idx >> 6; mm[p] = idx & 63;
    }
    auto issue_tile = [&](int st, int mbase) {
#pragma unroll
        for (int p = 0; p < 4; p++)
            cpasync16(&sK[st][dd[p] * SKT + mm[p]],
                      Kp + (long long)dd[p] * NTOK + mbase + mm[p]);
#pragma unroll
        for (int p = 0; p < 4; p++)
            cpasync16(&sV[st][dd[p] * SKT + mm[p]],
                      Vp + (long long)dd[p] * NTOK + mbase + mm[p]);
        cpcommit();
    };

    // Prologue: stage tiles 0 and 1 (overlaps with the inv computation).
    issue_tile(0, 0);
    issue_tile(1, 64);

    // Inline inverse L2 norms: thread tid handles one of the 128 rows this
    // head needs (64 q rows, then 64 k rows), summing its 36 ssq partials.
    {
        const int r = (tid < 64) ? (h * 64 + tid) : (512 + h * 64 + (tid - 64));
        const float* p = ssqp + ((long long)b * 1024 + r) * 36;
        float s = 0.0f;
#pragma unroll
        for (int j = 0; j < 36; j++) s += p[j];
        sInv[tid] = 1.0f / fmaxf(sqrtf(s), 1e-12f);
    }
    __syncthreads();
    const float* invQ = sInv;
    const float* invK = sInv + 64;

    // Q^T A-fragments for 32 rows (2 groups of 16), scaled by invQ*invK*lg2e.
    uint32_t qa[2][4][4];
    {
#pragma unroll
        for (int u = 0; u < 2; u++) {
            const int nA = n0 + w * 32 + u * 16 + g;
#pragma unroll
            for (int kk = 0; kk < 4; kk++) {
                const int ddq = kk * 16 + 2 * tg;
                const float s0 = invQ[ddq]     * invK[ddq]     * LG2E;
                const float s1 = invQ[ddq + 1] * invK[ddq + 1] * LG2E;
                const float s8 = invQ[ddq + 8] * invK[ddq + 8] * LG2E;
                const float s9 = invQ[ddq + 9] * invK[ddq + 9] * LG2E;
                qa[u][kk][0] = packh2(__half2float(Q[(long long)ddq * NTOK + nA]) * s0,
                                      __half2float(Q[(long long)(ddq + 1) * NTOK + nA]) * s1);
                qa[u][kk][1] = packh2(__half2float(Q[(long long)ddq * NTOK + nA + 8]) * s0,
                                      __half2float(Q[(long long)(ddq + 1) * NTOK + nA + 8]) * s1);
                qa[u][kk][2] = packh2(__half2float(Q[(long long)(ddq + 8) * NTOK + nA]) * s8,
                                      __half2float(Q[(long long)(ddq + 9) * NTOK + nA]) * s9);
                qa[u][kk][3] = packh2(__half2float(Q[(long long)(ddq + 8) * NTOK + nA + 8]) * s8,
                                      __half2float(Q[(long long)(ddq + 9) * NTOK + nA + 8]) * s9);
            }
        }
    }

    // O^T accumulators: all 64 d (4 m-tiles) x warp's 32 n (4 n-groups of 8).
    float oc[4][4][4];
#pragma unroll
    for (int mt = 0; mt < 4; mt++)
#pragma unroll
        for (int nt = 0; nt < 4; nt++)
#pragma unroll
            for (int j = 0; j < 4; j++) oc[mt][nt][j] = 0.0f;

    float rsum[4] = {0.0f, 0.0f, 0.0f, 0.0f};   // lane-partial row sums

    const int src_lo = 8 * tg;       // lane holding row 2tg of an 8-group
    const int src_hi = 8 * tg + 4;   // lane holding row 2tg+1

    const int NKV = NTOK / 64;       // 36
    int cur = 0;
    for (int t = 0; t < NKV; t++) {
        if (t + 1 < NKV)
            asm volatile("cp.async.wait_group 1;\n");
        else
            asm volatile("cp.async.wait_group 0;\n");
        __syncthreads();
        if (t + 2 < NKV) issue_tile((t + 2) % NST, (t + 2) * 64);

        const __half* cK = sK[cur];
        const __half* cV = sV[cur];

        // ---- Phase A: S = Q^T K (32 n-rows x 64 m per warp) ----
        float sc[2][8][4];
#pragma unroll
        for (int u = 0; u < 2; u++)
#pragma unroll
            for (int tt = 0; tt < 8; tt++)
#pragma unroll
                for (int j = 0; j < 4; j++) sc[u][tt][j] = 0.0f;

#pragma unroll
        for (int kk = 0; kk < 4; kk++) {
            const __half* krow = &cK[(kk * 16 + l_row) * SKT + l_col8];
#pragma unroll
            for (int tt = 0; tt < 8; tt += 2) {
                uint32_t b0, b1, b2, b3;
                ldmx4t(b0, b1, b2, b3, krow + tt * 8);   // K frags, tiles tt/tt+1
                mmah(sc[0][tt],     qa[0][kk], b0, b1);
                mmah(sc[0][tt + 1], qa[0][kk], b2, b3);
                mmah(sc[1][tt],     qa[1][kk], b0, b1);
                mmah(sc[1][tt + 1], qa[1][kk], b2, b3);
            }
        }

        // ---- Unshifted softmax numerators: P = exp2(sc) ----
        uint32_t ph[8][4];            // [m-tile][n-group u*2+r]
#pragma unroll
        for (int u = 0; u < 2; u++)
#pragma unroll
        for (int r = 0; r < 2; r++) {
            const int q4 = u * 2 + r;
            float ps = 0.0f;
#pragma unroll
            for (int tt = 0; tt < 8; tt++) {
                float e0 = exp2f(sc[u][tt][2 * r]);
                float e1 = exp2f(sc[u][tt][2 * r + 1]);
                ps += e0 + e1;
                ph[tt][q4] = packh2(e0, e1);
            }
            rsum[q4] += ps;           // lane-partial; reduced in epilogue
        }

        // ---- Phase B: O^T += V * P^T (each V fragment feeds 4 mma) ----
#pragma unroll
        for (int kk = 0; kk < 4; kk++) {
#pragma unroll
            for (int mt = 0; mt < 4; mt++) {
                uint32_t a[4];
                ldmx4(a, &cV[(mt * 16 + l_row) * SKT + kk * 16 + l_col8]);
#pragma unroll
                for (int nt = 0; nt < 4; nt++)
                    mmah(oc[mt][nt], a, ph[2 * kk][nt], ph[2 * kk + 1][nt]);
            }
        }

        cur = (cur + 1) % NST;
    }

    // ---- Epilogue: reduce rsum across the 4-lane groups, then normalize ----
    float iv[4][2];
#pragma unroll
    for (int nt = 0; nt < 4; nt++) {
        rsum[nt] += __shfl_xor_sync(0xffffffffu, rsum[nt], 1);
        rsum[nt] += __shfl_xor_sync(0xffffffffu, rsum[nt], 2);
        iv[nt][0] = 1.0f / __shfl_sync(0xffffffffu, rsum[nt], src_lo);
        iv[nt][1] = 1.0f / __shfl_sync(0xffffffffu, rsum[nt], src_hi);
    }

    __half* Op = outp + ((long long)(b * HID + h * 64)) * NTOK + n0 + w * 32;
#pragma unroll
    for (int mt = 0; mt < 4; mt++) {
#pragma unroll
        for (int nt = 0; nt < 4; nt++) {
            const int ncol = nt * 8 + 2 * tg;
            __half* p0 = Op + (long long)(mt * 16 + g) * NTOK + ncol;
            *(__half2*)p0 = __floats2half2_rn(oc[mt][nt][0] * iv[nt][0],
                                              oc[mt][nt][1] * iv[nt][1]);
            __half* p1 = Op + (long long)(mt * 16 + g + 8) * NTOK + ncol;
            *(__half2*)p1 = __floats2half2_rn(oc[mt][nt][2] * iv[nt][0],
                                              oc[mt][nt][3] * iv[nt][1]);
        }
    }
}

// ---------------------------------------------------------------------------
extern "C" void kernel_launch(void* const* d_in, const int* in_sizes, int n_in,
                              void* d_out, int out_size)
{
    const float* x      = (const float*)d_in[0];   // (2, 256, 48, 48)
    const float* w_qkv  = (const float*)d_in[1];   // (1536, 256)
    const float* w_proj = (const float*)d_in[2];   // (256, 512)
    const float* b_proj = (const float*)d_in[3];   // (256,)
    float* y = (float*)d_out;                      // (2, 256, 48, 48)

    __half *qkv_ptr = nullptr, *att_ptr = nullptr, *xh = nullptr,
           *wqh = nullptr, *wph = nullptr;
    float  *ssq_ptr = nullptr;
    cudaGetSymbolAddress((void**)&qkv_ptr, g_qkv);
    cudaGetSymbolAddress((void**)&att_ptr, g_att);
    cudaGetSymbolAddress((void**)&xh,  g_xh);
    cudaGetSymbolAddress((void**)&wqh, g_wqh);
    cudaGetSymbolAddress((void**)&wph, g_wph);
    cudaGetSymbolAddress((void**)&ssq_ptr, g_ssqp);

    // 0) convert inputs to fp16
    cvt3<<<(CVT_N1 + CVT_N2 + CVT_N3) / (256 * 8), 256>>>(x, w_qkv, w_proj);

    // 1) qkv = w_qkv @ x : [1536,256] x [256,2304] per batch, fp16 out.
    //    128x128 tiles (R15 speed) + fused ssq partials (36 slots/row).
    h16gemm<128, 128, 4, 2, __half, true>
        <<<dim3(NTOK / 128, QKV_M / 128, 2), 256>>>(
        wqh, xh, qkv_ptr, nullptr, ssq_ptr,
        QKV_M, NTOK, CIN,
        (long long)CIN * NTOK, (long long)QKV_M * NTOK);

    // 2) flash attention (inv norms computed inline from ssq partials):
    //    18 q-tiles x 16 (b,h) heads, 128 threads
    flash_attn_h<<<dim3(NTOK / 128, 16), 128>>>(qkv_ptr, ssq_ptr, att_ptr);

    // 3) y = w_proj @ att + bias : [256,512] x [512,2304] per batch, fp32 out.
    //    64x64 tiles -> 288 CTAs (halved A re-reads, 2x work per CTA).
    h16gemm<64, 64, 2, 2, float, false>
        <<<dim3(NTOK / 64, CIN / 64, 2), 128>>>(
        wph, att_ptr, y, b_proj, nullptr,
        CIN, NTOK, HID,
        (long long)HID * NTOK, (long long)CIN * NTOK);
}